// round 3
// baseline (speedup 1.0000x reference)
#include <cuda_runtime.h>

#define POOL 14
#define H 128
#define W 128
#define C 1024
#define R 256
#define C4 (C / 4)

// One CTA per (roi, py) output row: 14 px * 1024 ch, 256 threads (one float4
// channel-group each). x-side gather tuples precomputed into shared once.
// Depth-2 software pipeline: prefetch next px's 4 corner vectors while
// lerping the current one. __launch_bounds__(256,6) caps regs at 42 ->
// 6 CTAs/SM = 75% occupancy.
__global__ __launch_bounds__(256, 6) void roi_resize_kernel(
    const float4* __restrict__ img,   // [H, W, C4]
    const float*  __restrict__ rois,  // [R, 4]
    float4*       __restrict__ out)   // [R, POOL, POOL, C4]
{
    const int py = blockIdx.x;          // 0..13
    const int r  = blockIdx.y;          // 0..255
    const int c4 = threadIdx.x;         // 0..255

    __shared__ int   s_ax0[POOL];
    __shared__ int   s_ax1[POOL];
    __shared__ float s_fx [POOL];

    const int x1 = (int)rois[r * 4 + 0];
    const int y1 = (int)rois[r * 4 + 1];
    const int x2 = (int)rois[r * 4 + 2];
    const int y2 = (int)rois[r * 4 + 3];

    if (threadIdx.x < POOL) {
        const float ww = (float)(x2 - x1);
        const float src_x = (float)threadIdx.x * (ww * (1.0f / POOL));
        const int   x0 = (int)floorf(src_x);
        const int   x1i = min(x0 + 1, (x2 - x1) - 1);
        s_fx [threadIdx.x] = src_x - (float)x0;
        s_ax0[threadIdx.x] = min(max(x1 + x0, 0), W - 1);
        s_ax1[threadIdx.x] = min(max(x1 + x1i, 0), W - 1);
    }

    const float hh = (float)(y2 - y1);
    const float src_y = (float)py * (hh * (1.0f / POOL));
    const int   y0 = (int)floorf(src_y);
    const float fy = src_y - (float)y0;
    const int   y1i = min(y0 + 1, (y2 - y1) - 1);
    const int   ay0 = min(max(y1 + y0, 0), H - 1);
    const int   ay1 = min(max(y1 + y1i, 0), H - 1);

    __syncthreads();

    const float4* __restrict__ row0 = img + (size_t)(ay0 * W) * C4 + c4;
    const float4* __restrict__ row1 = img + (size_t)(ay1 * W) * C4 + c4;
    float4* __restrict__ orow = out + ((size_t)(r * POOL + py) * POOL) * C4 + c4;

    // prologue: prefetch px=0
    float4 v00 = row0[s_ax0[0] * C4];
    float4 v01 = row0[s_ax1[0] * C4];
    float4 v10 = row1[s_ax0[0] * C4];
    float4 v11 = row1[s_ax1[0] * C4];

    #pragma unroll
    for (int px = 0; px < POOL; px++) {
        const float fx = s_fx[px];
        const float4 c00 = v00, c01 = v01, c10 = v10, c11 = v11;

        // prefetch next iteration's corners before consuming current
        if (px + 1 < POOL) {
            const int nax0 = s_ax0[px + 1];
            const int nax1 = s_ax1[px + 1];
            v00 = row0[nax0 * C4];
            v01 = row0[nax1 * C4];
            v10 = row1[nax0 * C4];
            v11 = row1[nax1 * C4];
        }

        float4 o;
        {
            float top = c00.x + (c01.x - c00.x) * fx;
            float bot = c10.x + (c11.x - c10.x) * fx;
            o.x = top + (bot - top) * fy;
        }
        {
            float top = c00.y + (c01.y - c00.y) * fx;
            float bot = c10.y + (c11.y - c10.y) * fx;
            o.y = top + (bot - top) * fy;
        }
        {
            float top = c00.z + (c01.z - c00.z) * fx;
            float bot = c10.z + (c11.z - c10.z) * fx;
            o.z = top + (bot - top) * fy;
        }
        {
            float top = c00.w + (c01.w - c00.w) * fx;
            float bot = c10.w + (c11.w - c10.w) * fx;
            o.w = top + (bot - top) * fy;
        }

        __stcs(&orow[(size_t)px * C4], o);   // streaming write, skip L2 fill
    }
}

extern "C" void kernel_launch(void* const* d_in, const int* in_sizes, int n_in,
                              void* d_out, int out_size) {
    const float4* img  = (const float4*)d_in[0];
    const float*  rois = (const float*)d_in[1];
    float4*       out  = (float4*)d_out;

    dim3 grid(POOL, R);
    roi_resize_kernel<<<grid, 256>>>(img, rois, out);
}

// round 4
// speedup vs baseline: 1.0280x; 1.0280x over previous
#include <cuda_runtime.h>

#define POOL 14
#define H 128
#define W 128
#define C 1024
#define R 256
#define C4 (C / 4)

// One CTA per (roi, py) row. 256 threads = one float4 channel-group each.
// x-side gather tuples precomputed into shared. Full unroll over the 14 px
// (ptxas batches the loads -> high MLP). Zero-weight / duplicate-column
// corner loads are skipped exactly:
//   fx==0  -> v01,v11 unused (weight 0), substitute v00/v10  (bit-exact)
//   fy==0  -> v10,v11 unused, substitute                      (bit-exact)
//   ax1==ax0 / ay1==ay0 -> duplicate load, substitute         (bit-exact)
// ~24% fewer load wavefronts through L1tex, the binding pipe.
__global__ __launch_bounds__(256) void roi_resize_kernel(
    const float4* __restrict__ img,   // [H, W, C4]
    const float*  __restrict__ rois,  // [R, 4]
    float4*       __restrict__ out)   // [R, POOL, POOL, C4]
{
    const int py = blockIdx.x;          // 0..13
    const int r  = blockIdx.y;          // 0..255
    const int c4 = threadIdx.x;         // 0..255

    __shared__ int   s_ax0[POOL];
    __shared__ int   s_ax1[POOL];
    __shared__ float s_fx [POOL];

    const int x1 = (int)rois[r * 4 + 0];
    const int y1 = (int)rois[r * 4 + 1];
    const int x2 = (int)rois[r * 4 + 2];
    const int y2 = (int)rois[r * 4 + 3];

    if (threadIdx.x < POOL) {
        const float ww = (float)(x2 - x1);
        const float src_x = (float)threadIdx.x * (ww * (1.0f / POOL));
        const int   x0 = (int)floorf(src_x);
        const int   x1i = min(x0 + 1, (x2 - x1) - 1);
        s_fx [threadIdx.x] = src_x - (float)x0;
        s_ax0[threadIdx.x] = min(max(x1 + x0, 0), W - 1);
        s_ax1[threadIdx.x] = min(max(x1 + x1i, 0), W - 1);
    }

    const float hh = (float)(y2 - y1);
    const float src_y = (float)py * (hh * (1.0f / POOL));
    const int   y0 = (int)floorf(src_y);
    const float fy = src_y - (float)y0;
    const int   y1i = min(y0 + 1, (y2 - y1) - 1);
    const int   ay0 = min(max(y1 + y0, 0), H - 1);
    const int   ay1 = min(max(y1 + y1i, 0), H - 1);

    __syncthreads();

    const float4* __restrict__ row0 = img + (size_t)(ay0 * W) * C4 + c4;
    const float4* __restrict__ row1 = img + (size_t)(ay1 * W) * C4 + c4;
    float4* __restrict__ orow = out + ((size_t)(r * POOL + py) * POOL) * C4 + c4;

    // y-side load needed only if row1 actually contributes
    const bool needy = (fy != 0.0f) && (ay1 != ay0);

    #pragma unroll
    for (int px = 0; px < POOL; px++) {
        const int   ax0 = s_ax0[px];
        const int   ax1 = s_ax1[px];
        const float fx  = s_fx[px];
        const bool  needx = (fx != 0.0f) && (ax1 != ax0);

        const float4 v00 = row0[ax0 * C4];
        const float4 v01 = needx ? row0[ax1 * C4] : v00;
        const float4 v10 = needy ? row1[ax0 * C4] : v00;
        const float4 v11 = (needx && needy) ? row1[ax1 * C4]
                                            : (needx ? v01 : v10);

        float4 o;
        {
            float top = v00.x + (v01.x - v00.x) * fx;
            float bot = v10.x + (v11.x - v10.x) * fx;
            o.x = top + (bot - top) * fy;
        }
        {
            float top = v00.y + (v01.y - v00.y) * fx;
            float bot = v10.y + (v11.y - v10.y) * fx;
            o.y = top + (bot - top) * fy;
        }
        {
            float top = v00.z + (v01.z - v00.z) * fx;
            float bot = v10.z + (v11.z - v10.z) * fx;
            o.z = top + (bot - top) * fy;
        }
        {
            float top = v00.w + (v01.w - v00.w) * fx;
            float bot = v10.w + (v11.w - v10.w) * fx;
            o.w = top + (bot - top) * fy;
        }

        __stcs(&orow[(size_t)px * C4], o);
    }
}

extern "C" void kernel_launch(void* const* d_in, const int* in_sizes, int n_in,
                              void* d_out, int out_size) {
    const float4* img  = (const float4*)d_in[0];
    const float*  rois = (const float*)d_in[1];
    float4*       out  = (float4*)d_out;

    dim3 grid(POOL, R);
    roi_resize_kernel<<<grid, 256>>>(img, rois, out);
}